// round 8
// baseline (speedup 1.0000x reference)
#include <cuda_runtime.h>
#include <cuda_bf16.h>
#include <cstdint>

#define KK 4096
#define NPIX (64*32*256)
#define DELTA_D 1e-3f
#define SROW 272
#define B_OFF (128 * SROW)
#define SM_TOTAL (2 * 128 * SROW)
#define NEGINF __int_as_float(0xff800000)
#define POSINF __int_as_float(0x7f800000)

__device__ float g_zrest[NPIX];
__device__ float g_zflat[2][16384*32];   // ping-pong (fixes cross-CTA race)
__device__ float g_zsq[2][16384];
__device__ float g_wsq[KK];
__device__ __nv_bfloat16 g_zbf[16384*128];
__device__ __nv_bfloat16 g_ebf[4096*128];
__device__ int g_cnt[16384*16];
__device__ int g_cand[16384*16*8];

__device__ __forceinline__ uint32_t smem_u32(const void* p) {
    uint32_t a;
    asm("{ .reg .u64 t; cvta.to.shared.u64 t, %1; cvt.u32.u64 %0, t; }"
        : "=r"(a) : "l"(p));
    return a;
}

// ---------- fused init ----------
__global__ void k_init(const float* __restrict__ z, const float* __restrict__ w) {
    int bid = blockIdx.x, tid = threadIdx.x;
    if (bid < 2048) {
        int i = bid * 256 + tid;
        g_zrest[i] = z[i];
    } else if (bid < 2064) {
        int r = (bid - 2048) * 256 + tid;      // code 0..4095
        const float* p = w + r * 32;
        float s = 0.f;
#pragma unroll
        for (int c = 0; c < 32; c++) s = __fadd_rn(s, __fmul_rn(p[c], p[c]));
        g_wsq[r] = s;
        __nv_bfloat16* eb = g_ebf + (size_t)r * 128;
#pragma unroll
        for (int c = 0; c < 32; c++) {
            float v = p[c];
            __nv_bfloat16 hi = __float2bfloat16(v);
            __nv_bfloat16 lo = __float2bfloat16(v - __bfloat162float(hi));
            eb[c] = hi; eb[32 + c] = hi; eb[64 + c] = lo;
        }
        float h = -0.5f * s;
        __nv_bfloat16 hh = __float2bfloat16(h);
        __nv_bfloat16 hl = __float2bfloat16(h - __bfloat162float(hh));
        eb[96] = hh; eb[97] = hl;
        for (int i2 = 98; i2 < 128; i2++) eb[i2] = __float2bfloat16(0.f);
    } else if (bid < 2072) {
        // level-0 prep: warp per token, lane = channel
        int warp = tid >> 5, lane = tid & 31;
        int t = (bid - 2064) * 8 + warp;
        const float* base = z + (t * 32 + lane) * 256;
        float s = 0.f;
        for (int dy = 0; dy < 16; dy++)
            for (int dx = 0; dx < 16; dx++)
                s = __fadd_rn(s, base[dy * 16 + dx]);
        float zd = __fmul_rn(s, 1.f / 256.f);
        g_zflat[0][t * 32 + lane] = zd;
        __nv_bfloat16 hi = __float2bfloat16(zd);
        __nv_bfloat16 lo = __float2bfloat16(zd - __bfloat162float(hi));
        __nv_bfloat16* zb = g_zbf + (size_t)t * 128;
        zb[lane] = hi; zb[32 + lane] = lo; zb[64 + lane] = hi;
        float q = __fmul_rn(zd, zd);
#pragma unroll
        for (int off = 16; off; off >>= 1)
            q = __fadd_rn(q, __shfl_xor_sync(0xffffffffu, q, off));
        if (lane == 0) g_zsq[0][t] = q;
    } else {
        // z-side constant columns for all rows: 96,97 = 1.0, pad 0
        int r = (bid - 2072) * 256 + tid;      // 0..16383
        __nv_bfloat16* zb = g_zbf + (size_t)r * 128;
        __nv_bfloat16 one = __float2bfloat16(1.f);
        zb[96] = one; zb[97] = one;
        for (int i2 = 98; i2 < 128; i2++) zb[i2] = __float2bfloat16(0.f);
    }
}

// ---------- tensor GEMM + skip-scan candidate collection (all levels) -------
__global__ void __launch_bounds__(256) k_gemm(int ntok) {
    extern __shared__ char dsm[];
    char* At = dsm;
    char* Bt = dsm + B_OFF;
    int tid = threadIdx.x;
    int wid = tid >> 5, lane = tid & 31;
    int g = lane >> 2, q = lane & 3;
    int tb = blockIdx.x * 128;
    int split = blockIdx.y;

    // stage A once (clamped rows)
    {
        int r = tid >> 1, h = tid & 1;
        int tr = tb + r; if (tr > ntok - 1) tr = ntok - 1;
        const uint4* src = (const uint4*)(g_zbf + (size_t)tr * 128 + h * 64);
        uint4* dst = (uint4*)(At + r * SROW + h * 128);
#pragma unroll
        for (int j = 0; j < 8; j++) dst[j] = src[j];
    }

    uint32_t sA = smem_u32(At) + (wid * 16 + (lane & 15)) * SROW + ((lane >> 4) * 16);
    uint32_t sB = smem_u32(Bt) + ((((lane >> 4) << 3) + (lane & 7)) * SROW)
                + (((lane >> 3) & 1) * 16);

    int t0 = tb + wid * 16 + g, t1 = t0 + 8;
    bool live0 = t0 < ntok, live1 = t1 < ntok;
    int cb0 = ((t0 * 4 + split) * 4 + q) * 8;
    int cb1 = ((t1 * 4 + split) * 4 + q) * 8;
    float best0 = NEGINF, best1 = NEGINF;
    int cnt0 = 0, cnt1 = 0;

    for (int it = 0; it < 8; it++) {
        int code0 = split * 1024 + it * 128;
        __syncthreads();
        {
            int r = tid >> 1, h = tid & 1;
            const uint4* src = (const uint4*)(g_ebf + (size_t)(code0 + r) * 128 + h * 64);
            uint4* dst = (uint4*)(Bt + r * SROW + h * 128);
#pragma unroll
            for (int j = 0; j < 8; j++) dst[j] = src[j];
        }
        __syncthreads();

        float acc[16][4];
#pragma unroll
        for (int nt = 0; nt < 16; nt++)
#pragma unroll
            for (int c = 0; c < 4; c++) acc[nt][c] = 0.f;

#pragma unroll
        for (int k = 0; k < 8; k++) {
            uint32_t a0, a1, a2, a3;
            asm volatile("ldmatrix.sync.aligned.m8n8.x4.shared.b16 {%0,%1,%2,%3}, [%4];"
                         : "=r"(a0), "=r"(a1), "=r"(a2), "=r"(a3)
                         : "r"(sA + k * 32));
#pragma unroll
            for (int j = 0; j < 8; j++) {
                uint32_t b0, b1, b2, b3;
                asm volatile("ldmatrix.sync.aligned.m8n8.x4.shared.b16 {%0,%1,%2,%3}, [%4];"
                             : "=r"(b0), "=r"(b1), "=r"(b2), "=r"(b3)
                             : "r"(sB + j * (16 * SROW) + k * 32));
                asm volatile(
                    "mma.sync.aligned.m16n8k16.row.col.f32.bf16.bf16.f32 "
                    "{%0,%1,%2,%3}, {%4,%5,%6,%7}, {%8,%9}, {%0,%1,%2,%3};"
                    : "+f"(acc[2*j][0]), "+f"(acc[2*j][1]),
                      "+f"(acc[2*j][2]), "+f"(acc[2*j][3])
                    : "r"(a0), "r"(a1), "r"(a2), "r"(a3), "r"(b0), "r"(b1));
                asm volatile(
                    "mma.sync.aligned.m16n8k16.row.col.f32.bf16.bf16.f32 "
                    "{%0,%1,%2,%3}, {%4,%5,%6,%7}, {%8,%9}, {%0,%1,%2,%3};"
                    : "+f"(acc[2*j+1][0]), "+f"(acc[2*j+1][1]),
                      "+f"(acc[2*j+1][2]), "+f"(acc[2*j+1][3])
                    : "r"(a0), "r"(a1), "r"(a2), "r"(a3), "r"(b2), "r"(b3));
            }
        }

        // skip-scan epilogue with purge: branchless max, rare collection pass
        float m0 = NEGINF, m1 = NEGINF;
#pragma unroll
        for (int nt = 0; nt < 16; nt++) {
            m0 = fmaxf(m0, fmaxf(acc[nt][0], acc[nt][1]));
            m1 = fmaxf(m1, fmaxf(acc[nt][2], acc[nt][3]));
        }
        if (live0 && m0 >= best0 - DELTA_D) {
            if (m0 - DELTA_D > best0) cnt0 = 0;       // all prior candidates stale
            float nb = fmaxf(best0, m0), thr = nb - DELTA_D;
#pragma unroll
            for (int nt = 0; nt < 16; nt++)
#pragma unroll
                for (int c = 0; c < 2; c++)
                    if (acc[nt][c] >= thr) {
                        if (cnt0 < 8) g_cand[cb0 + cnt0] = code0 + nt * 8 + q * 2 + c;
                        cnt0++;
                    }
            best0 = nb;
        }
        if (live1 && m1 >= best1 - DELTA_D) {
            if (m1 - DELTA_D > best1) cnt1 = 0;
            float nb = fmaxf(best1, m1), thr = nb - DELTA_D;
#pragma unroll
            for (int nt = 0; nt < 16; nt++)
#pragma unroll
                for (int c = 0; c < 2; c++)
                    if (acc[nt][c + 2] >= thr) {
                        if (cnt1 < 8) g_cand[cb1 + cnt1] = code0 + nt * 8 + q * 2 + c;
                        cnt1++;
                    }
            best1 = nb;
        }
    }
    if (live0) g_cnt[(t0 * 4 + split) * 4 + q] = cnt0;
    if (live1) g_cnt[(t1 * 4 + split) * 4 + q] = cnt1;
}

// ---------- exact fp32 distance + warp rerank ----------
__device__ __forceinline__ float exact_d(const float* __restrict__ zr, float zq,
                                         const float* __restrict__ emb, int k) {
    const float* e = emb + k * 32;
    float acc = 0.f;
#pragma unroll
    for (int c = 0; c < 32; c++) acc = __fmaf_rn(zr[c], e[c], acc);
    float s1 = __fadd_rn(zq, g_wsq[k]);
    return __fadd_rn(s1, __fmul_rn(-2.f, acc));
}

__device__ __forceinline__ int rerank_token(int gt, const float* __restrict__ emb,
                                            const float* __restrict__ zflat,
                                            const float* __restrict__ zsq) {
    int lane = threadIdx.x & 31;
    const float* zr = zflat + gt * 32;
    float zq = zsq[gt];
    float bd = POSINF; int bk = 0x7fffffff;
    bool fb = false;
    if (lane < 16) {
        int c = g_cnt[gt * 16 + lane];
        if (c > 8) { fb = true; c = 8; }
        for (int i = 0; i < c; i++) {
            int k = g_cand[(gt * 16 + lane) * 8 + i];
            float d = exact_d(zr, zq, emb, k);
            if (d < bd || (d == bd && k < bk)) { bd = d; bk = k; }
        }
    }
    if (__ballot_sync(0xffffffffu, fb)) {
        for (int k = lane; k < 4096; k += 32) {
            float d = exact_d(zr, zq, emb, k);
            if (d < bd || (d == bd && k < bk)) { bd = d; bk = k; }
        }
    }
#pragma unroll
    for (int off = 16; off; off >>= 1) {
        float od = __shfl_xor_sync(0xffffffffu, bd, off);
        int   ok = __shfl_xor_sync(0xffffffffu, bk, off);
        if (od < bd || (od == bd && ok < bk)) { bd = od; bk = ok; }
    }
    return __shfl_sync(0xffffffffu, bk, 0);
}

// ---------- cubic weights ----------
template<int PN>
__device__ __forceinline__ void cubw(int o, float* w) {
    if (PN == 1) { w[0] = 1.f; return; }
    float s = __fadd_rn(__fmul_rn(__fadd_rn((float)o, 0.5f), (float)PN / 16.f), -0.5f);
    float tot = 0.f;
#pragma unroll
    for (int i = 0; i < PN; i++) {
        float x = fabsf(s - (float)i);
        float v;
        if (x >= 2.f)      v = 0.f;
        else if (x >= 1.f) v = ((-0.5f * x + 2.5f) * x - 4.f) * x + 2.f;
        else               v = ((1.5f * x - 2.5f) * x) * x + 1.f;
        w[i] = v; tot += v;
    }
#pragma unroll
    for (int i = 0; i < PN; i++) w[i] = w[i] / tot;
}

// ---------- fused rerank + up-sample + residual + next-level prep ----------
// rp = read ping-pong index for zflat/zsq; writes go to rp^1.
template<int PN, int PNN>
__global__ void __launch_bounds__(256) k_up(const float* __restrict__ emb,
                                            const float* __restrict__ outPrev,
                                            float* __restrict__ outCur,
                                            int isFirst, int rp) {
    constexpr int NT = PN * PN;
    constexpr int SUB = 16 / PNN;
    __shared__ int   tok_s[NT];
    __shared__ float ew[NT][33];
    __shared__ float zt[32][256];
    int b = blockIdx.x;
    int tid = threadIdx.x;
    int wid = tid >> 5, lane = tid & 31;
    const float* zrf = g_zflat[rp];
    const float* zrq = g_zsq[rp];
    float* zwf = g_zflat[rp ^ 1];
    float* zwq = g_zsq[rp ^ 1];

    // Phase A: exact rerank (reads ONLY the rp buffers — race-free)
    for (int t = wid; t < NT; t += 8) {
        int bk = rerank_token(b * NT + t, emb, zrf, zrq);
        if (lane == 0) tok_s[t] = bk;
    }
    __syncthreads();

    // Phase B: stage gathered embeddings
    for (int idx = tid; idx < NT * 8; idx += 256) {
        int token = idx >> 3, seg = idx & 7;
        float4 v = *(const float4*)(emb + tok_s[token] * 32 + seg * 4);
        ew[token][seg*4+0] = v.x; ew[token][seg*4+1] = v.y;
        ew[token][seg*4+2] = v.z; ew[token][seg*4+3] = v.w;
    }
    __syncthreads();

    // Phase C: bicubic up + out + zrest
    int y = tid >> 4, x = tid & 15;
    float wy[PN], wx[PN];
    cubw<PN>(y, wy);
    cubw<PN>(x, wx);
#pragma unroll
    for (int c = 0; c < 32; c++) {
        float acc = 0.f;
#pragma unroll
        for (int j = 0; j < PN; j++) {
            float tmp = 0.f;
#pragma unroll
            for (int i = 0; i < PN; i++) tmp += wx[i] * ew[j * PN + i][c];
            acc += wy[j] * tmp;
        }
        int idx = (b * 32 + c) * 256 + y * 16 + x;
        float prev = isFirst ? 0.f : outPrev[idx];
        outCur[idx] = prev + acc;
        float nz = g_zrest[idx] - acc;
        g_zrest[idx] = nz;
        zt[c][tid] = nz;
    }
    __syncthreads();

    // Phase D: next-level downsample -> rp^1 buffers + zbf
    if (tid < PNN * PNN) {
        int ty2 = tid / PNN, tx2 = tid % PNN;
        float buf[32];
        float zqacc = 0.f;
#pragma unroll
        for (int c = 0; c < 32; c++) {
            float s = 0.f;
            for (int dy = 0; dy < SUB; dy++)
                for (int dx = 0; dx < SUB; dx++)
                    s = __fadd_rn(s, zt[c][(ty2 * SUB + dy) * 16 + tx2 * SUB + dx]);
            float zd = __fmul_rn(s, 1.f / (float)(SUB * SUB));
            buf[c] = zd;
            zqacc = __fadd_rn(zqacc, __fmul_rn(zd, zd));
        }
        int row = b * PNN * PNN + tid;
        float* dst = zwf + (size_t)row * 32;
#pragma unroll
        for (int s8 = 0; s8 < 8; s8++)
            *(float4*)(dst + s8 * 4) = make_float4(buf[s8*4], buf[s8*4+1],
                                                   buf[s8*4+2], buf[s8*4+3]);
        zwq[row] = zqacc;
        __nv_bfloat16* zb = g_zbf + (size_t)row * 128;
#pragma unroll
        for (int c = 0; c < 32; c++) {
            float v = buf[c];
            __nv_bfloat16 hi = __float2bfloat16(v);
            __nv_bfloat16 lo = __float2bfloat16(v - __bfloat162float(hi));
            zb[c] = hi; zb[32 + c] = lo; zb[64 + c] = hi;
        }
    }
}

// ---------- last level: rerank + gather + accumulate ----------
__global__ void __launch_bounds__(256) k_up_last(const float* __restrict__ emb,
                                                 const float* __restrict__ outPrev,
                                                 float* __restrict__ outCur, int rp) {
    __shared__ int tok_s[256];
    int b = blockIdx.x, tid = threadIdx.x;
    int wid = tid >> 5, lane = tid & 31;
    const float* zrf = g_zflat[rp];
    const float* zrq = g_zsq[rp];
    for (int t = wid; t < 256; t += 8) {
        int bk = rerank_token(b * 256 + t, emb, zrf, zrq);
        if (lane == 0) tok_s[t] = bk;
    }
    __syncthreads();
    const float* e = emb + tok_s[tid] * 32;
#pragma unroll
    for (int c = 0; c < 32; c++) {
        int idx = (b * 32 + c) * 256 + tid;
        outCur[idx] = outPrev[idx] + e[c];
    }
}

extern "C" void kernel_launch(void* const* d_in, const int* in_sizes, int n_in,
                              void* d_out, int out_size) {
    const float* z = (const float*)d_in[0];
    const float* w = (const float*)d_in[1];
    float* out = (float*)d_out;

    cudaFuncSetAttribute(k_gemm, cudaFuncAttributeMaxDynamicSharedMemorySize, SM_TOTAL);

    k_init<<<2136, 256>>>(z, w);

    const int ntok[5] = {64, 256, 1024, 4096, 16384};
    for (int l = 0; l < 5; l++) {
        int n = ntok[l];
        dim3 g((n + 127) / 128, 4);
        k_gemm<<<g, 256, SM_TOTAL>>>(n);

        int rp = l & 1;
        float* cur = out + (size_t)l * NPIX;
        const float* prev = (l == 0) ? out : out + (size_t)(l - 1) * NPIX;
        if      (l == 0) k_up<1, 2 ><<<64, 256>>>(w, prev, cur, 1, rp);
        else if (l == 1) k_up<2, 4 ><<<64, 256>>>(w, prev, cur, 0, rp);
        else if (l == 2) k_up<4, 8 ><<<64, 256>>>(w, prev, cur, 0, rp);
        else if (l == 3) k_up<8, 16><<<64, 256>>>(w, prev, cur, 0, rp);
        else             k_up_last<<<64, 256>>>(w, prev, cur, rp);
    }
}

// round 9
// speedup vs baseline: 1.7849x; 1.7849x over previous
#include <cuda_runtime.h>
#include <cstdint>

#define KK 4096
#define NPIX (64*32*256)
#define POSINF __int_as_float(0x7f800000)

__device__ float g_zrest[NPIX];
__device__ float g_zflat[16384*32];
__device__ float g_zsq[16384];
__device__ float g_wsq[KK];
__device__ float g_pd[32768];
__device__ int   g_pi[32768];

typedef unsigned long long ull;

// ---------- fused init: zrest copy + wsq + level-0 prep ----------
__global__ void k_init(const float* __restrict__ z, const float* __restrict__ w) {
    int bid = blockIdx.x, tid = threadIdx.x;
    if (bid < 2048) {
        int i = bid * 256 + tid;
        g_zrest[i] = z[i];
    } else if (bid < 2064) {
        int r = (bid - 2048) * 256 + tid;
        const float* p = w + r * 32;
        float s = 0.f;
#pragma unroll
        for (int c = 0; c < 32; c++) s = __fadd_rn(s, __fmul_rn(p[c], p[c]));
        g_wsq[r] = s;
    } else {
        int warp = tid >> 5, lane = tid & 31;
        int t = (bid - 2064) * 8 + warp;          // 0..63
        const float* base = z + (t * 32 + lane) * 256;
        float s = 0.f;
        for (int dy = 0; dy < 16; dy++)
            for (int dx = 0; dx < 16; dx++)
                s = __fadd_rn(s, base[dy * 16 + dx]);
        float zd = __fmul_rn(s, 1.f / 256.f);
        g_zflat[t * 32 + lane] = zd;
        float q = __fmul_rn(zd, zd);
#pragma unroll
        for (int off = 16; off; off >>= 1)
            q = __fadd_rn(q, __shfl_xor_sync(0xffffffffu, q, off));
        if (lane == 0) g_zsq[t] = q;
    }
}

// ---------- dist+argmin: 32 tok x 128 codes, conflict-free f32x2 FMA --------
// 128 threads: tx = tid&15 (8 codes), ty = tid>>4 (4 tokens = 2 f32x2 pairs)
__global__ void __launch_bounds__(128) k_dist(const float* __restrict__ emb,
                                              int cps, int iters) {
    __shared__ float zs[32][32];            // [c][token]
    __shared__ ulonglong2 es2[4][32][16];   // [h][c][tx] : codes tx*8+2h, +2h+1 (dup'd)
    __shared__ float ws[128];
    int tid = threadIdx.x;
    int tx = tid & 15, ty = tid >> 4;
    int tb = blockIdx.x * 32;

    // stage z tile (c-major): 32 tok x 4 parts = 128 slots, 1/thread
    {
        int tok = tid >> 2, part = tid & 3;
        const float4* p = (const float4*)(g_zflat + (tb + tok) * 32 + part * 8);
        float4 a = p[0], b4 = p[1];
        int c0 = part * 8;
        zs[c0+0][tok]=a.x;  zs[c0+1][tok]=a.y;  zs[c0+2][tok]=a.z;  zs[c0+3][tok]=a.w;
        zs[c0+4][tok]=b4.x; zs[c0+5][tok]=b4.y; zs[c0+6][tok]=b4.z; zs[c0+7][tok]=b4.w;
    }
    float zq[4];
#pragma unroll
    for (int j = 0; j < 4; j++) zq[j] = g_zsq[tb + ty * 4 + j];

    float bd[4]; int bk[4];
#pragma unroll
    for (int j = 0; j < 4; j++) { bd[j] = POSINF; bk[j] = 0; }

    int kbase = blockIdx.y * cps;
    for (int it = 0; it < iters; it++) {
        int kb = kbase + it * 128;
        __syncthreads();
        // stage e tile pre-duplicated: 64 code-pairs x 4 parts = 256 slots
        for (int s = tid; s < 256; s += 128) {
            int pair = s >> 2, part = s & 3;
            int txi = pair & 15, h = pair >> 4;
            int c0 = part * 8;
            int code0 = kb + txi * 8 + 2 * h;
            const float4* p0 = (const float4*)(emb + code0 * 32 + part * 8);
            const float4* p1 = (const float4*)(emb + (code0 + 1) * 32 + part * 8);
            float4 a0 = p0[0], a1 = p0[1];
            float4 b0 = p1[0], b1 = p1[1];
            float e0[8] = {a0.x,a0.y,a0.z,a0.w,a1.x,a1.y,a1.z,a1.w};
            float e1[8] = {b0.x,b0.y,b0.z,b0.w,b1.x,b1.y,b1.z,b1.w};
#pragma unroll
            for (int i = 0; i < 8; i++) {
                ull d0, d1;
                asm("mov.b64 %0, {%1, %1};" : "=l"(d0) : "f"(e0[i]));
                asm("mov.b64 %0, {%1, %1};" : "=l"(d1) : "f"(e1[i]));
                es2[h][c0 + i][txi] = make_ulonglong2(d0, d1);
            }
        }
        ws[tid] = g_wsq[kb + tid];
        __syncthreads();

        ull acc[2][8];
#pragma unroll
        for (int p = 0; p < 2; p++)
#pragma unroll
            for (int k = 0; k < 8; k++) acc[p][k] = 0ull;

#pragma unroll 8
        for (int c = 0; c < 32; c++) {
            ulonglong2 zp2 = *(const ulonglong2*)&zs[c][ty * 4];
            ull zp[2] = {zp2.x, zp2.y};
            ulonglong2 e0 = es2[0][c][tx];
            ulonglong2 e1 = es2[1][c][tx];
            ulonglong2 e2 = es2[2][c][tx];
            ulonglong2 e3 = es2[3][c][tx];
            ull ed[8] = {e0.x, e0.y, e1.x, e1.y, e2.x, e2.y, e3.x, e3.y};
#pragma unroll
            for (int p = 0; p < 2; p++)
#pragma unroll
                for (int k = 0; k < 8; k++)
                    asm("fma.rn.f32x2 %0, %1, %2, %0;"
                        : "+l"(acc[p][k]) : "l"(zp[p]), "l"(ed[k]));
        }

        // distances + best update (codes ascending within thread)
#pragma unroll
        for (int p = 0; p < 2; p++) {
#pragma unroll
            for (int k = 0; k < 8; k++) {
                float lo, hi;
                asm("mov.b64 {%0, %1}, %2;" : "=f"(lo), "=f"(hi) : "l"(acc[p][k]));
                int kk = kb + tx * 8 + k;
                float wv = ws[tx * 8 + k];
                float d0 = __fadd_rn(__fadd_rn(zq[2*p],   wv), __fmul_rn(-2.f, lo));
                float d1 = __fadd_rn(__fadd_rn(zq[2*p+1], wv), __fmul_rn(-2.f, hi));
                if (d0 < bd[2*p])   { bd[2*p]   = d0; bk[2*p]   = kk; }
                if (d1 < bd[2*p+1]) { bd[2*p+1] = d1; bk[2*p+1] = kk; }
            }
        }
    }

    // reduce across the 16 tx lanes (tie -> lowest code index)
#pragma unroll
    for (int j = 0; j < 4; j++) {
        float d = bd[j]; int k = bk[j];
#pragma unroll
        for (int off = 8; off; off >>= 1) {
            float od = __shfl_xor_sync(0xffffffffu, d, off, 16);
            int   ok = __shfl_xor_sync(0xffffffffu, k, off, 16);
            if (od < d || (od == d && ok < k)) { d = od; k = ok; }
        }
        if (tx == 0) {
            int t = tb + ty * 4 + j;
            g_pd[t * gridDim.y + blockIdx.y] = d;
            g_pi[t * gridDim.y + blockIdx.y] = k;
        }
    }
}

// ---------- cubic (jax Keys a=-0.5) weights, renormalized ----------
template<int PN>
__device__ __forceinline__ void cubw(int o, float* w) {
    if (PN == 1) { w[0] = 1.f; return; }
    float s = __fadd_rn(__fmul_rn(__fadd_rn((float)o, 0.5f), (float)PN / 16.f), -0.5f);
    float tot = 0.f;
#pragma unroll
    for (int i = 0; i < PN; i++) {
        float x = fabsf(s - (float)i);
        float v;
        if (x >= 2.f)      v = 0.f;
        else if (x >= 1.f) v = ((-0.5f * x + 2.5f) * x - 4.f) * x + 2.f;
        else               v = ((1.5f * x - 2.5f) * x) * x + 1.f;
        w[i] = v; tot += v;
    }
#pragma unroll
    for (int i = 0; i < PN; i++) w[i] = w[i] / tot;
}

// ---------- fused: ksplit-reduce + gather + bicubic + zrest + next prep -----
template<int PN, int PNN>
__global__ void __launch_bounds__(256) k_up(const float* __restrict__ emb,
                                            const float* __restrict__ outPrev,
                                            float* __restrict__ outCur,
                                            int isFirst, int KS) {
    constexpr int NT = PN * PN;
    constexpr int SUB = 16 / PNN;
    __shared__ float pdp[512];
    __shared__ int   pip[512];
    __shared__ int   tok_s[NT];
    __shared__ float ew[NT][33];
    __shared__ float zt[32][256];
    int b = blockIdx.x;
    int tid = threadIdx.x;

    int tot = NT * KS;
    for (int i = tid; i < tot; i += 256) {
        pdp[i] = g_pd[b * tot + i];
        pip[i] = g_pi[b * tot + i];
    }
    __syncthreads();
    if (tid < NT) {
        float bdv = pdp[tid * KS]; int bkv = pip[tid * KS];
        for (int s = 1; s < KS; s++) {
            float d = pdp[tid * KS + s]; int k = pip[tid * KS + s];
            if (d < bdv || (d == bdv && k < bkv)) { bdv = d; bkv = k; }
        }
        tok_s[tid] = bkv;
    }
    __syncthreads();

    for (int idx = tid; idx < NT * 8; idx += 256) {
        int token = idx >> 3, seg = idx & 7;
        float4 v = *(const float4*)(emb + tok_s[token] * 32 + seg * 4);
        ew[token][seg*4+0] = v.x; ew[token][seg*4+1] = v.y;
        ew[token][seg*4+2] = v.z; ew[token][seg*4+3] = v.w;
    }
    __syncthreads();

    int y = tid >> 4, x = tid & 15;
    float wy[PN], wx[PN];
    cubw<PN>(y, wy);
    cubw<PN>(x, wx);
#pragma unroll
    for (int c = 0; c < 32; c++) {
        float acc = 0.f;
#pragma unroll
        for (int j = 0; j < PN; j++) {
            float tmp = 0.f;
#pragma unroll
            for (int i = 0; i < PN; i++) tmp += wx[i] * ew[j * PN + i][c];
            acc += wy[j] * tmp;
        }
        int idx = (b * 32 + c) * 256 + y * 16 + x;
        float prev = isFirst ? 0.f : outPrev[idx];
        outCur[idx] = prev + acc;
        float nz = g_zrest[idx] - acc;
        g_zrest[idx] = nz;
        zt[c][tid] = nz;
    }
    __syncthreads();

    if (tid < PNN * PNN) {
        int ty2 = tid / PNN, tx2 = tid % PNN;
        float buf[32];
        float zqacc = 0.f;
#pragma unroll
        for (int c = 0; c < 32; c++) {
            float s = 0.f;
            for (int dy = 0; dy < SUB; dy++)
                for (int dx = 0; dx < SUB; dx++)
                    s = __fadd_rn(s, zt[c][(ty2 * SUB + dy) * 16 + tx2 * SUB + dx]);
            float zd = __fmul_rn(s, 1.f / (float)(SUB * SUB));
            buf[c] = zd;
            zqacc = __fadd_rn(zqacc, __fmul_rn(zd, zd));
        }
        int row = b * PNN * PNN + tid;
        float* dst = g_zflat + (size_t)row * 32;
#pragma unroll
        for (int s8 = 0; s8 < 8; s8++)
            *(float4*)(dst + s8 * 4) = make_float4(buf[s8*4], buf[s8*4+1],
                                                   buf[s8*4+2], buf[s8*4+3]);
        g_zsq[row] = zqacc;
    }
}

// ---------- last level: reduce + gather + accumulate ----------
__global__ void __launch_bounds__(256) k_up_last(const float* __restrict__ emb,
                                                 const float* __restrict__ outPrev,
                                                 float* __restrict__ outCur, int KS) {
    __shared__ float pdp[1024];
    __shared__ int   pip[1024];
    __shared__ int   tok_s[256];
    int b = blockIdx.x, tid = threadIdx.x;
    int tot = 256 * KS;
    for (int i = tid; i < tot; i += 256) {
        pdp[i] = g_pd[b * tot + i];
        pip[i] = g_pi[b * tot + i];
    }
    __syncthreads();
    {
        float bdv = pdp[tid * KS]; int bkv = pip[tid * KS];
        for (int s = 1; s < KS; s++) {
            float d = pdp[tid * KS + s]; int k = pip[tid * KS + s];
            if (d < bdv || (d == bdv && k < bkv)) { bdv = d; bkv = k; }
        }
        tok_s[tid] = bkv;
    }
    __syncthreads();
    const float* e = emb + tok_s[tid] * 32;
#pragma unroll
    for (int c = 0; c < 32; c++) {
        int idx = (b * 32 + c) * 256 + tid;
        outCur[idx] = outPrev[idx] + e[c];
    }
}

extern "C" void kernel_launch(void* const* d_in, const int* in_sizes, int n_in,
                              void* d_out, int out_size) {
    const float* z = (const float*)d_in[0];
    const float* w = (const float*)d_in[1];
    float* out = (float*)d_out;

    k_init<<<2072, 256>>>(z, w);

    const int ntok[5] = {64, 256, 1024, 4096, 16384};
    const int KSs[5]  = {32, 32, 16, 4, 2};

    for (int l = 0; l < 5; l++) {
        int KS = KSs[l];
        int cps = KK / KS;
        int iters = cps / 128;
        dim3 g(ntok[l] / 32, KS);
        k_dist<<<g, 128>>>(w, cps, iters);

        float* cur = out + (size_t)l * NPIX;
        const float* prev = (l == 0) ? out : out + (size_t)(l - 1) * NPIX;
        if      (l == 0) k_up<1, 2 ><<<64, 256>>>(w, prev, cur, 1, KS);
        else if (l == 1) k_up<2, 4 ><<<64, 256>>>(w, prev, cur, 0, KS);
        else if (l == 2) k_up<4, 8 ><<<64, 256>>>(w, prev, cur, 0, KS);
        else if (l == 3) k_up<8, 16><<<64, 256>>>(w, prev, cur, 0, KS);
        else             k_up_last<<<64, 256>>>(w, prev, cur, KS);
    }
}

// round 10
// speedup vs baseline: 2.3107x; 1.2946x over previous
#include <cuda_runtime.h>
#include <cstdint>

#define KK 4096
#define NPIX (64*32*256)
#define POSINF __int_as_float(0x7f800000)

__device__ float g_zrest[NPIX];
__device__ float g_zflat[16384*32];
__device__ float g_zsq[16384];
__device__ float g_wsq[KK];
__device__ float g_pd[32768];
__device__ int   g_pi[32768];

typedef unsigned long long ull;

// ---------- fused init: zrest copy + wsq + level-0 prep ----------
__global__ void k_init(const float* __restrict__ z, const float* __restrict__ w) {
    int bid = blockIdx.x, tid = threadIdx.x;
    if (bid < 2048) {
        int i = bid * 256 + tid;
        g_zrest[i] = z[i];
    } else if (bid < 2064) {
        int r = (bid - 2048) * 256 + tid;
        const float* p = w + r * 32;
        float s = 0.f;
#pragma unroll
        for (int c = 0; c < 32; c++) s = __fadd_rn(s, __fmul_rn(p[c], p[c]));
        g_wsq[r] = s;
    } else {
        int warp = tid >> 5, lane = tid & 31;
        int t = (bid - 2064) * 8 + warp;          // 0..63
        const float* base = z + (t * 32 + lane) * 256;
        float s = 0.f;
        for (int dy = 0; dy < 16; dy++)
            for (int dx = 0; dx < 16; dx++)
                s = __fadd_rn(s, base[dy * 16 + dx]);
        float zd = __fmul_rn(s, 1.f / 256.f);
        g_zflat[t * 32 + lane] = zd;
        float q = __fmul_rn(zd, zd);
#pragma unroll
        for (int off = 16; off; off >>= 1)
            q = __fadd_rn(q, __shfl_xor_sync(0xffffffffu, q, off));
        if (lane == 0) g_zsq[t] = q;
    }
}

// ---------- dist+argmin: 64 tok x 128 codes, 256 thr, conflict-free f32x2 ---
// tx = tid&15 (8 codes), ty = tid>>4 in 0..15 (4 tokens = 2 f32x2 pairs)
__global__ void __launch_bounds__(256) k_dist(const float* __restrict__ emb,
                                              int cps, int iters) {
    __shared__ float zs[32][64];            // [c][token]
    __shared__ ulonglong2 es2[4][32][16];   // [h][c][tx]: codes tx*8+2h, +2h+1 (dup'd)
    __shared__ float ws[128];
    int tid = threadIdx.x;
    int tx = tid & 15, ty = tid >> 4;
    int tb = blockIdx.x * 64;

    // stage z tile (c-major): 64 tok x 4 parts = 256 slots, 1/thread
    {
        int tok = tid >> 2, part = tid & 3;
        const float4* p = (const float4*)(g_zflat + (tb + tok) * 32 + part * 8);
        float4 a = p[0], b4 = p[1];
        int c0 = part * 8;
        zs[c0+0][tok]=a.x;  zs[c0+1][tok]=a.y;  zs[c0+2][tok]=a.z;  zs[c0+3][tok]=a.w;
        zs[c0+4][tok]=b4.x; zs[c0+5][tok]=b4.y; zs[c0+6][tok]=b4.z; zs[c0+7][tok]=b4.w;
    }
    float zq[4];
#pragma unroll
    for (int j = 0; j < 4; j++) zq[j] = g_zsq[tb + ty * 4 + j];

    float bd[4]; int bk[4];
#pragma unroll
    for (int j = 0; j < 4; j++) { bd[j] = POSINF; bk[j] = 0; }

    int kbase = blockIdx.y * cps;
    for (int it = 0; it < iters; it++) {
        int kb = kbase + it * 128;
        __syncthreads();
        // stage e tile pre-duplicated: 64 code-pairs x 4 parts = 256 slots, 1/thread
        {
            int pair = tid >> 2, part = tid & 3;
            int txi = pair & 15, h = pair >> 4;
            int c0 = part * 8;
            int code0 = kb + txi * 8 + 2 * h;
            const float4* p0 = (const float4*)(emb + code0 * 32 + part * 8);
            const float4* p1 = (const float4*)(emb + (code0 + 1) * 32 + part * 8);
            float4 a0 = p0[0], a1 = p0[1];
            float4 b0 = p1[0], b1 = p1[1];
            float e0[8] = {a0.x,a0.y,a0.z,a0.w,a1.x,a1.y,a1.z,a1.w};
            float e1[8] = {b0.x,b0.y,b0.z,b0.w,b1.x,b1.y,b1.z,b1.w};
#pragma unroll
            for (int i = 0; i < 8; i++) {
                ull d0, d1;
                asm("mov.b64 %0, {%1, %1};" : "=l"(d0) : "f"(e0[i]));
                asm("mov.b64 %0, {%1, %1};" : "=l"(d1) : "f"(e1[i]));
                es2[h][c0 + i][txi] = make_ulonglong2(d0, d1);
            }
        }
        if (tid < 128) ws[tid] = g_wsq[kb + tid];
        __syncthreads();

        ull acc[2][8];
#pragma unroll
        for (int p = 0; p < 2; p++)
#pragma unroll
            for (int k = 0; k < 8; k++) acc[p][k] = 0ull;

#pragma unroll 8
        for (int c = 0; c < 32; c++) {
            ulonglong2 zp2 = *(const ulonglong2*)&zs[c][ty * 4];
            ull zp[2] = {zp2.x, zp2.y};
            ulonglong2 e0 = es2[0][c][tx];
            ulonglong2 e1 = es2[1][c][tx];
            ulonglong2 e2 = es2[2][c][tx];
            ulonglong2 e3 = es2[3][c][tx];
            ull ed[8] = {e0.x, e0.y, e1.x, e1.y, e2.x, e2.y, e3.x, e3.y};
#pragma unroll
            for (int p = 0; p < 2; p++)
#pragma unroll
                for (int k = 0; k < 8; k++)
                    asm("fma.rn.f32x2 %0, %1, %2, %0;"
                        : "+l"(acc[p][k]) : "l"(zp[p]), "l"(ed[k]));
        }

        // distances + best update (codes ascending within thread)
#pragma unroll
        for (int p = 0; p < 2; p++) {
#pragma unroll
            for (int k = 0; k < 8; k++) {
                float lo, hi;
                asm("mov.b64 {%0, %1}, %2;" : "=f"(lo), "=f"(hi) : "l"(acc[p][k]));
                int kk = kb + tx * 8 + k;
                float wv = ws[tx * 8 + k];
                float d0 = __fadd_rn(__fadd_rn(zq[2*p],   wv), __fmul_rn(-2.f, lo));
                float d1 = __fadd_rn(__fadd_rn(zq[2*p+1], wv), __fmul_rn(-2.f, hi));
                if (d0 < bd[2*p])   { bd[2*p]   = d0; bk[2*p]   = kk; }
                if (d1 < bd[2*p+1]) { bd[2*p+1] = d1; bk[2*p+1] = kk; }
            }
        }
    }

    // reduce across the 16 tx lanes (tie -> lowest code index)
#pragma unroll
    for (int j = 0; j < 4; j++) {
        float d = bd[j]; int k = bk[j];
#pragma unroll
        for (int off = 8; off; off >>= 1) {
            float od = __shfl_xor_sync(0xffffffffu, d, off, 16);
            int   ok = __shfl_xor_sync(0xffffffffu, k, off, 16);
            if (od < d || (od == d && ok < k)) { d = od; k = ok; }
        }
        if (tx == 0) {
            int t = tb + ty * 4 + j;
            g_pd[t * gridDim.y + blockIdx.y] = d;
            g_pi[t * gridDim.y + blockIdx.y] = k;
        }
    }
}

// ---------- cubic (jax Keys a=-0.5) weights, renormalized ----------
template<int PN>
__device__ __forceinline__ void cubw(int o, float* w) {
    if (PN == 1) { w[0] = 1.f; return; }
    float s = __fadd_rn(__fmul_rn(__fadd_rn((float)o, 0.5f), (float)PN / 16.f), -0.5f);
    float tot = 0.f;
#pragma unroll
    for (int i = 0; i < PN; i++) {
        float x = fabsf(s - (float)i);
        float v;
        if (x >= 2.f)      v = 0.f;
        else if (x >= 1.f) v = ((-0.5f * x + 2.5f) * x - 4.f) * x + 2.f;
        else               v = ((1.5f * x - 2.5f) * x) * x + 1.f;
        w[i] = v; tot += v;
    }
#pragma unroll
    for (int i = 0; i < PN; i++) w[i] = w[i] / tot;
}

// ---------- fused: ksplit-reduce + gather + bicubic + zrest + next prep -----
template<int PN, int PNN>
__global__ void __launch_bounds__(256) k_up(const float* __restrict__ emb,
                                            const float* __restrict__ outPrev,
                                            float* __restrict__ outCur,
                                            int isFirst, int KS) {
    constexpr int NT = PN * PN;
    constexpr int SUB = 16 / PNN;
    __shared__ float pdp[512];
    __shared__ int   pip[512];
    __shared__ int   tok_s[NT];
    __shared__ float ew[NT][33];
    __shared__ float zt[32][256];
    int b = blockIdx.x;
    int tid = threadIdx.x;

    int tot = NT * KS;
    for (int i = tid; i < tot; i += 256) {
        pdp[i] = g_pd[b * tot + i];
        pip[i] = g_pi[b * tot + i];
    }
    __syncthreads();
    if (tid < NT) {
        float bdv = pdp[tid * KS]; int bkv = pip[tid * KS];
        for (int s = 1; s < KS; s++) {
            float d = pdp[tid * KS + s]; int k = pip[tid * KS + s];
            if (d < bdv || (d == bdv && k < bkv)) { bdv = d; bkv = k; }
        }
        tok_s[tid] = bkv;
    }
    __syncthreads();

    for (int idx = tid; idx < NT * 8; idx += 256) {
        int token = idx >> 3, seg = idx & 7;
        float4 v = *(const float4*)(emb + tok_s[token] * 32 + seg * 4);
        ew[token][seg*4+0] = v.x; ew[token][seg*4+1] = v.y;
        ew[token][seg*4+2] = v.z; ew[token][seg*4+3] = v.w;
    }
    __syncthreads();

    int y = tid >> 4, x = tid & 15;
    float wy[PN], wx[PN];
    cubw<PN>(y, wy);
    cubw<PN>(x, wx);
#pragma unroll
    for (int c = 0; c < 32; c++) {
        float acc = 0.f;
#pragma unroll
        for (int j = 0; j < PN; j++) {
            float tmp = 0.f;
#pragma unroll
            for (int i = 0; i < PN; i++) tmp += wx[i] * ew[j * PN + i][c];
            acc += wy[j] * tmp;
        }
        int idx = (b * 32 + c) * 256 + y * 16 + x;
        float prev = isFirst ? 0.f : outPrev[idx];
        outCur[idx] = prev + acc;
        float nz = g_zrest[idx] - acc;
        g_zrest[idx] = nz;
        zt[c][tid] = nz;
    }
    __syncthreads();

    if (tid < PNN * PNN) {
        int ty2 = tid / PNN, tx2 = tid % PNN;
        float buf[32];
        float zqacc = 0.f;
#pragma unroll
        for (int c = 0; c < 32; c++) {
            float s = 0.f;
            for (int dy = 0; dy < SUB; dy++)
                for (int dx = 0; dx < SUB; dx++)
                    s = __fadd_rn(s, zt[c][(ty2 * SUB + dy) * 16 + tx2 * SUB + dx]);
            float zd = __fmul_rn(s, 1.f / (float)(SUB * SUB));
            buf[c] = zd;
            zqacc = __fadd_rn(zqacc, __fmul_rn(zd, zd));
        }
        int row = b * PNN * PNN + tid;
        float* dst = g_zflat + (size_t)row * 32;
#pragma unroll
        for (int s8 = 0; s8 < 8; s8++)
            *(float4*)(dst + s8 * 4) = make_float4(buf[s8*4], buf[s8*4+1],
                                                   buf[s8*4+2], buf[s8*4+3]);
        g_zsq[row] = zqacc;
    }
}

// ---------- last level: reduce + gather + accumulate ----------
__global__ void __launch_bounds__(256) k_up_last(const float* __restrict__ emb,
                                                 const float* __restrict__ outPrev,
                                                 float* __restrict__ outCur, int KS) {
    __shared__ float pdp[1024];
    __shared__ int   pip[1024];
    __shared__ int   tok_s[256];
    int b = blockIdx.x, tid = threadIdx.x;
    int tot = 256 * KS;
    for (int i = tid; i < tot; i += 256) {
        pdp[i] = g_pd[b * tot + i];
        pip[i] = g_pi[b * tot + i];
    }
    __syncthreads();
    {
        float bdv = pdp[tid * KS]; int bkv = pip[tid * KS];
        for (int s = 1; s < KS; s++) {
            float d = pdp[tid * KS + s]; int k = pip[tid * KS + s];
            if (d < bdv || (d == bdv && k < bkv)) { bdv = d; bkv = k; }
        }
        tok_s[tid] = bkv;
    }
    __syncthreads();
    const float* e = emb + tok_s[tid] * 32;
#pragma unroll
    for (int c = 0; c < 32; c++) {
        int idx = (b * 32 + c) * 256 + tid;
        outCur[idx] = outPrev[idx] + e[c];
    }
}

extern "C" void kernel_launch(void* const* d_in, const int* in_sizes, int n_in,
                              void* d_out, int out_size) {
    const float* z = (const float*)d_in[0];
    const float* w = (const float*)d_in[1];
    float* out = (float*)d_out;

    k_init<<<2072, 256>>>(z, w);

    const int ntok[5] = {64, 256, 1024, 4096, 16384};
    const int KSs[5]  = {32, 32, 16, 4, 2};

    for (int l = 0; l < 5; l++) {
        int KS = KSs[l];
        int cps = KK / KS;
        int iters = cps / 128;
        dim3 g(ntok[l] / 64, KS);
        k_dist<<<g, 256>>>(w, cps, iters);

        float* cur = out + (size_t)l * NPIX;
        const float* prev = (l == 0) ? out : out + (size_t)(l - 1) * NPIX;
        if      (l == 0) k_up<1, 2 ><<<64, 256>>>(w, prev, cur, 1, KS);
        else if (l == 1) k_up<2, 4 ><<<64, 256>>>(w, prev, cur, 0, KS);
        else if (l == 2) k_up<4, 8 ><<<64, 256>>>(w, prev, cur, 0, KS);
        else if (l == 3) k_up<8, 16><<<64, 256>>>(w, prev, cur, 0, KS);
        else             k_up_last<<<64, 256>>>(w, prev, cur, KS);
    }
}